// round 6
// baseline (speedup 1.0000x reference)
#include <cuda_runtime.h>
#include <cstdint>

// CtaPostAttnMixer: 4-step fixed-boundary heat diffusion along seq dim.
// x: (B=4, L=8192, D=1024) fp32.
//
// R5: cp.async.bulk (16KB contiguous stages) -> 3-stage smem ring + mbarrier.
// Decouples DRAM in-flight bytes from registers (R3/R4 were MLP-limited at
// 72.6% DRAM because register prefetch was consumed under-latency).
// Compute: 12-row register window as 3 quads with period-3 static rotation
// (unrolled x3 => no shift MOVs). 9-tap closed-form conv for interior rows;
// explicit 4-step iteration for the 8-row edge windows (left from smem,
// right from the last chunk's final register window).

constexpr int B  = 4;
constexpr int L  = 8192;
constexpr int D  = 1024;
constexpr int D4 = D / 4;

constexpr int L_CHUNK = 60;          // interior rows per block
constexpr int NCHUNK  = 137;         // 136*60 + 24 = 8184 interior rows
constexpr int NSTAGES = 3;
constexpr int STAGE_ROWS  = 4;
constexpr int STAGE_F4    = STAGE_ROWS * D4;       // 1024 float4
constexpr int STAGE_BYTES = STAGE_ROWS * D * 4;    // 16384

// Taps of ((1-2a) + a*s + a*s^-1)^4 with a = 0.1 (symmetric, sums to 1)
constexpr float T0 = 0.0001f;
constexpr float T1 = 0.0032f;
constexpr float T2 = 0.0388f;
constexpr float T3 = 0.2144f;
constexpr float T4 = 0.4870f;

extern __shared__ float4 dyn_smem[];   // NSTAGES * STAGE_F4 float4

// ---------------- PTX helpers ----------------
__device__ __forceinline__ uint32_t smem_u32(const void* p) {
    uint32_t r;
    asm("{ .reg .u64 t; cvta.to.shared.u64 t, %1; cvt.u32.u64 %0, t; }"
        : "=r"(r) : "l"(p));
    return r;
}
__device__ __forceinline__ void mbar_init(uint32_t a, uint32_t cnt) {
    asm volatile("mbarrier.init.shared.b64 [%0], %1;" :: "r"(a), "r"(cnt) : "memory");
}
__device__ __forceinline__ void mbar_expect_tx(uint32_t a, uint32_t bytes) {
    asm volatile("mbarrier.arrive.expect_tx.shared.b64 _, [%0], %1;"
                 :: "r"(a), "r"(bytes) : "memory");
}
__device__ __forceinline__ void bulk_g2s(uint32_t dst, const void* src,
                                         uint32_t bytes, uint32_t mbar) {
    asm volatile(
        "cp.async.bulk.shared::cta.global.mbarrier::complete_tx::bytes "
        "[%0], [%1], %2, [%3];"
        :: "r"(dst), "l"(src), "r"(bytes), "r"(mbar) : "memory");
}
__device__ __forceinline__ void mbar_wait(uint32_t a, uint32_t parity) {
    asm volatile(
        "{\n\t.reg .pred P1;\n\t"
        "WLOOP%=:\n\t"
        "mbarrier.try_wait.parity.acquire.cta.shared::cta.b64 P1, [%0], %1, 0x989680;\n\t"
        "@P1 bra WDONE%=;\n\t"
        "bra WLOOP%=;\n\t"
        "WDONE%=:\n\t}"
        :: "r"(a), "r"(parity) : "memory");
}

// ---------------- math ----------------
__device__ __forceinline__ float4 conv9(const float4 r[9]) {
    float4 o;
    o.x = T4 * r[4].x + T3 * (r[3].x + r[5].x) + T2 * (r[2].x + r[6].x)
        + T1 * (r[1].x + r[7].x) + T0 * (r[0].x + r[8].x);
    o.y = T4 * r[4].y + T3 * (r[3].y + r[5].y) + T2 * (r[2].y + r[6].y)
        + T1 * (r[1].y + r[7].y) + T0 * (r[0].y + r[8].y);
    o.z = T4 * r[4].z + T3 * (r[3].z + r[5].z) + T2 * (r[2].z + r[6].z)
        + T1 * (r[1].z + r[7].z) + T0 * (r[0].z + r[8].z);
    o.w = T4 * r[4].w + T3 * (r[3].w + r[5].w) + T2 * (r[2].w + r[6].w)
        + T1 * (r[1].w + r[7].w) + T0 * (r[0].w + r[8].w);
    return o;
}

// 4-step explicit edge iteration on an 8-row window; e[0] (left) / e[7]
// (right) act as the fixed global boundary within the dependency cone.
__device__ __forceinline__ void edge_iter(float4 e[8]) {
    const float a = 0.1f;
#pragma unroll
    for (int s = 0; s < 4; ++s) {
        float4 prev = e[0];
#pragma unroll
        for (int i = 1; i < 7; ++i) {
            float4 cur = e[i], nb = e[i + 1], nv;
            nv.x = cur.x + a * (nb.x - 2.0f * cur.x + prev.x);
            nv.y = cur.y + a * (nb.y - 2.0f * cur.y + prev.y);
            nv.z = cur.z + a * (nb.z - 2.0f * cur.z + prev.z);
            nv.w = cur.w + a * (nb.w - 2.0f * cur.w + prev.w);
            e[i] = nv;
            prev = cur;
        }
    }
}

// One group: window = (q[A_]=rows l-4..l-1, q[B_]=rows l..l+3); incoming
// stage t (rows l+4..l+7) -> q[C_]; emit outputs l..l+3; window becomes
// (q[B_], q[C_]).
template <int A_, int B_, int C_>
__device__ __forceinline__ void run_body(
    float4 q[3][4], int t, int l, int last_stage,
    uint32_t mb0, uint32_t sm0, const char* src_base,
    const float4* smem_tid, float4* yb_tid, int tid)
{
    const int slot = t % NSTAGES;
    mbar_wait(mb0 + 8u * slot, (uint32_t)((t / NSTAGES) & 1));

    const float4* sp = smem_tid + slot * STAGE_F4;
#pragma unroll
    for (int r = 0; r < STAGE_ROWS; ++r)
        q[C_][r] = sp[r * D4];

    __syncthreads();   // all lanes done reading this slot

    if (tid == 0 && t + NSTAGES <= last_stage) {
        mbar_expect_tx(mb0 + 8u * slot, STAGE_BYTES);
        bulk_g2s(sm0 + (uint32_t)slot * STAGE_BYTES,
                 src_base + (size_t)(t + NSTAGES) * STAGE_BYTES,
                 STAGE_BYTES, mb0 + 8u * slot);
    }

    float4* yrow = yb_tid + (size_t)l * D4;
#pragma unroll
    for (int j = 0; j < 4; ++j) {
        float4 r[9];
#pragma unroll
        for (int k = 0; k < 9; ++k) {
            const int i = j + k;
            r[k] = (i < 4) ? q[A_][i] : (i < 8) ? q[B_][i - 4] : q[C_][i - 8];
        }
        yrow[(size_t)j * D4] = conv9(r);
    }
}

__global__ __launch_bounds__(256, 4) void mixer_kernel(
    const float* __restrict__ x, float* __restrict__ y)
{
    __shared__ uint64_t mbar[NSTAGES];

    const int tid   = threadIdx.x;
    const int chunk = blockIdx.x;
    const int b     = blockIdx.y;

    const size_t base = (size_t)b * L * D;
    const float4* __restrict__ xb = reinterpret_cast<const float4*>(x + base);
    float4*       __restrict__ yb = reinterpret_cast<float4*>(y + base);

    const int l0      = 4 + chunk * L_CHUNK;
    const int ngroups = (chunk == NCHUNK - 1) ? 6 : 15;   // both % 3 == 0
    const int last_stage = ngroups + 1;                   // stages 0..ngroups+1

    const uint32_t mb0 = smem_u32(&mbar[0]);
    const uint32_t sm0 = smem_u32(dyn_smem);
    const char* src_base = (const char*)(xb + (size_t)(l0 - 4) * D4);
    const float4* smem_tid = dyn_smem + tid;
    float4* yb_tid = yb + tid;

    if (tid == 0) {
#pragma unroll
        for (int s = 0; s < NSTAGES; ++s) mbar_init(mb0 + 8u * s, 1);
    }
    __syncthreads();

    if (tid == 0) {
#pragma unroll
        for (int t = 0; t < NSTAGES; ++t) {
            mbar_expect_tx(mb0 + 8u * t, STAGE_BYTES);
            bulk_g2s(sm0 + (uint32_t)t * STAGE_BYTES,
                     src_base + (size_t)t * STAGE_BYTES,
                     STAGE_BYTES, mb0 + 8u * t);
        }
    }

    // Wait for stages 0,1 (rows l0-4 .. l0+3)
    mbar_wait(mb0 + 0u, 0u);
    mbar_wait(mb0 + 8u, 0u);

    // Left boundary: rows 0..7 are stages 0,1 of chunk 0.
    if (chunk == 0) {
        float4 e[8];
#pragma unroll
        for (int r = 0; r < 4; ++r) e[r]     = smem_tid[r * D4];
#pragma unroll
        for (int r = 0; r < 4; ++r) e[4 + r] = smem_tid[STAGE_F4 + r * D4];
        edge_iter(e);
#pragma unroll
        for (int k = 0; k < 4; ++k)
            yb_tid[(size_t)k * D4] = e[k];   // rows 0..3 (e[0] = fixed x[0])
    }

    // Prologue window: q[0] = rows l0-4..l0-1, q[1] = rows l0..l0+3
    float4 q[3][4];
#pragma unroll
    for (int r = 0; r < 4; ++r) q[0][r] = smem_tid[r * D4];
#pragma unroll
    for (int r = 0; r < 4; ++r) q[1][r] = smem_tid[STAGE_F4 + r * D4];

    __syncthreads();   // everyone done reading slots 0,1

    if (tid == 0) {    // refill slots 0,1 with stages 3,4 (always exist)
#pragma unroll
        for (int t = NSTAGES; t < NSTAGES + 2; ++t) {
            const int slot = t % NSTAGES;
            mbar_expect_tx(mb0 + 8u * slot, STAGE_BYTES);
            bulk_g2s(sm0 + (uint32_t)slot * STAGE_BYTES,
                     src_base + (size_t)t * STAGE_BYTES,
                     STAGE_BYTES, mb0 + 8u * slot);
        }
    }

    // Main loop: bodies consume stage t = g+2; rotation period 3.
    int l = l0;
    int t = 2;
#pragma unroll 1
    for (int g = 0; g < ngroups; g += 3) {
        run_body<0, 1, 2>(q, t, l, last_stage, mb0, sm0, src_base, smem_tid, yb_tid, tid);
        ++t; l += 4;
        run_body<1, 2, 0>(q, t, l, last_stage, mb0, sm0, src_base, smem_tid, yb_tid, tid);
        ++t; l += 4;
        run_body<2, 0, 1>(q, t, l, last_stage, mb0, sm0, src_base, smem_tid, yb_tid, tid);
        ++t; l += 4;
    }

    // Right boundary: final window (q[0], q[1]) = rows L-8..L-1 for the last
    // chunk (ngroups % 3 == 0 -> rotation back to start).
    if (chunk == NCHUNK - 1) {
        float4 e[8];
#pragma unroll
        for (int r = 0; r < 4; ++r) { e[r] = q[0][r]; e[4 + r] = q[1][r]; }
        edge_iter(e);
#pragma unroll
        for (int k = 0; k < 4; ++k)
            yb_tid[(size_t)(L - 4 + k) * D4] = e[4 + k];  // rows L-4..L-1
    }
}

extern "C" void kernel_launch(void* const* d_in, const int* in_sizes, int n_in,
                              void* d_out, int out_size)
{
    const float* x = (const float*)d_in[0];
    float*       y = (float*)d_out;

    static bool attr_set = false;
    if (!attr_set) {
        cudaFuncSetAttribute(mixer_kernel,
                             cudaFuncAttributeMaxDynamicSharedMemorySize,
                             NSTAGES * STAGE_BYTES);
        attr_set = true;
    }

    mixer_kernel<<<dim3(NCHUNK, B), 256, NSTAGES * STAGE_BYTES>>>(x, y);
}

// round 9
// speedup vs baseline: 1.0071x; 1.0071x over previous
#include <cuda_runtime.h>
#include <cstdint>

// CtaPostAttnMixer: 4-step fixed-boundary heat diffusion along seq dim.
// x: (B=4, L=8192, D=1024) fp32.
//
// R6: deep TMA ring — 6 stages x 16KB (96KB smem/block), 2 blocks/SM,
// chunks of 120 rows, grid 69x4=276 = one wave. Prefetch coverage = 5
// DRAM-paced bodies (~5500 cyc) >> DRAM latency, fixing the 73%-DRAM
// plateau of R4/R5 (coverage was ~2 bodies). Streaming stores for y.
// Interior rows: closed-form 9-tap conv of (0.1 s^-1 + 0.8 + 0.1 s)^4.
// Edges: explicit 4-step iteration on 8-row windows (left from smem stages
// 0-1 of chunk 0; right from last chunk's final register window).

constexpr int B  = 4;
constexpr int L  = 8192;
constexpr int D  = 1024;
constexpr int D4 = D / 4;

constexpr int L_CHUNK = 120;         // interior rows per block
constexpr int NCHUNK  = 69;          // 68*120 + 24 = 8184 interior rows
constexpr int NSTAGES = 6;
constexpr int STAGE_ROWS  = 4;
constexpr int STAGE_F4    = STAGE_ROWS * D4;       // 1024 float4
constexpr int STAGE_BYTES = STAGE_ROWS * D * 4;    // 16384
constexpr int RING_BYTES  = NSTAGES * STAGE_BYTES; // 98304

// Taps of ((1-2a) + a*s + a*s^-1)^4 with a = 0.1 (symmetric, sums to 1)
constexpr float T0 = 0.0001f;
constexpr float T1 = 0.0032f;
constexpr float T2 = 0.0388f;
constexpr float T3 = 0.2144f;
constexpr float T4 = 0.4870f;

extern __shared__ float4 dyn_smem[];   // NSTAGES * STAGE_F4 float4

// ---------------- PTX helpers ----------------
__device__ __forceinline__ uint32_t smem_u32(const void* p) {
    uint32_t r;
    asm("{ .reg .u64 t; cvta.to.shared.u64 t, %1; cvt.u32.u64 %0, t; }"
        : "=r"(r) : "l"(p));
    return r;
}
__device__ __forceinline__ void mbar_init(uint32_t a, uint32_t cnt) {
    asm volatile("mbarrier.init.shared.b64 [%0], %1;" :: "r"(a), "r"(cnt) : "memory");
}
__device__ __forceinline__ void mbar_expect_tx(uint32_t a, uint32_t bytes) {
    asm volatile("mbarrier.arrive.expect_tx.shared.b64 _, [%0], %1;"
                 :: "r"(a), "r"(bytes) : "memory");
}
__device__ __forceinline__ void bulk_g2s(uint32_t dst, const void* src,
                                         uint32_t bytes, uint32_t mbar) {
    asm volatile(
        "cp.async.bulk.shared::cta.global.mbarrier::complete_tx::bytes "
        "[%0], [%1], %2, [%3];"
        :: "r"(dst), "l"(src), "r"(bytes), "r"(mbar) : "memory");
}
__device__ __forceinline__ void mbar_wait(uint32_t a, uint32_t parity) {
    asm volatile(
        "{\n\t.reg .pred P1;\n\t"
        "WLOOP%=:\n\t"
        "mbarrier.try_wait.parity.acquire.cta.shared::cta.b64 P1, [%0], %1, 0x989680;\n\t"
        "@P1 bra WDONE%=;\n\t"
        "bra WLOOP%=;\n\t"
        "WDONE%=:\n\t}"
        :: "r"(a), "r"(parity) : "memory");
}

// ---------------- math ----------------
__device__ __forceinline__ float4 conv9(const float4 r[9]) {
    float4 o;
    o.x = T4 * r[4].x + T3 * (r[3].x + r[5].x) + T2 * (r[2].x + r[6].x)
        + T1 * (r[1].x + r[7].x) + T0 * (r[0].x + r[8].x);
    o.y = T4 * r[4].y + T3 * (r[3].y + r[5].y) + T2 * (r[2].y + r[6].y)
        + T1 * (r[1].y + r[7].y) + T0 * (r[0].y + r[8].y);
    o.z = T4 * r[4].z + T3 * (r[3].z + r[5].z) + T2 * (r[2].z + r[6].z)
        + T1 * (r[1].z + r[7].z) + T0 * (r[0].z + r[8].z);
    o.w = T4 * r[4].w + T3 * (r[3].w + r[5].w) + T2 * (r[2].w + r[6].w)
        + T1 * (r[1].w + r[7].w) + T0 * (r[0].w + r[8].w);
    return o;
}

// 4-step explicit edge iteration on an 8-row window; e[0] (left) / e[7]
// (right) act as the fixed global boundary within the dependency cone.
__device__ __forceinline__ void edge_iter(float4 e[8]) {
    const float a = 0.1f;
#pragma unroll
    for (int s = 0; s < 4; ++s) {
        float4 prev = e[0];
#pragma unroll
        for (int i = 1; i < 7; ++i) {
            float4 cur = e[i], nb = e[i + 1], nv;
            nv.x = cur.x + a * (nb.x - 2.0f * cur.x + prev.x);
            nv.y = cur.y + a * (nb.y - 2.0f * cur.y + prev.y);
            nv.z = cur.z + a * (nb.z - 2.0f * cur.z + prev.z);
            nv.w = cur.w + a * (nb.w - 2.0f * cur.w + prev.w);
            e[i] = nv;
            prev = cur;
        }
    }
}

// One group: window = (q[A_]=rows l-4..l-1, q[B_]=rows l..l+3); incoming
// stage t (rows l+4..l+7) -> q[C_]; emit outputs l..l+3; window becomes
// (q[B_], q[C_]).
template <int A_, int B_, int C_>
__device__ __forceinline__ void run_body(
    float4 q[3][4], int t, int l, int last_stage,
    uint32_t mb0, uint32_t sm0, const char* src_base,
    const float4* smem_tid, float4* yb_tid, int tid)
{
    const int slot = t % NSTAGES;
    mbar_wait(mb0 + 8u * slot, (uint32_t)((t / NSTAGES) & 1));

    const float4* sp = smem_tid + slot * STAGE_F4;
#pragma unroll
    for (int r = 0; r < STAGE_ROWS; ++r)
        q[C_][r] = sp[r * D4];

    __syncthreads();   // all lanes done reading this slot

    if (tid == 0 && t + NSTAGES <= last_stage) {
        mbar_expect_tx(mb0 + 8u * slot, STAGE_BYTES);
        bulk_g2s(sm0 + (uint32_t)slot * STAGE_BYTES,
                 src_base + (size_t)(t + NSTAGES) * STAGE_BYTES,
                 STAGE_BYTES, mb0 + 8u * slot);
    }

    float4* yrow = yb_tid + (size_t)l * D4;
#pragma unroll
    for (int j = 0; j < 4; ++j) {
        float4 r[9];
#pragma unroll
        for (int k = 0; k < 9; ++k) {
            const int i = j + k;
            r[k] = (i < 4) ? q[A_][i] : (i < 8) ? q[B_][i - 4] : q[C_][i - 8];
        }
        __stcs(yrow + (size_t)j * D4, conv9(r));   // streaming store
    }
}

__global__ __launch_bounds__(256, 2) void mixer_kernel(
    const float* __restrict__ x, float* __restrict__ y)
{
    __shared__ uint64_t mbar[NSTAGES];

    const int tid   = threadIdx.x;
    const int chunk = blockIdx.x;
    const int b     = blockIdx.y;

    const size_t base = (size_t)b * L * D;
    const float4* __restrict__ xb = reinterpret_cast<const float4*>(x + base);
    float4*       __restrict__ yb = reinterpret_cast<float4*>(y + base);

    const int l0      = 4 + chunk * L_CHUNK;
    const int ngroups = (chunk == NCHUNK - 1) ? 6 : 30;   // both % 3 == 0
    const int last_stage = ngroups + 1;                   // stages 0..ngroups+1

    const uint32_t mb0 = smem_u32(&mbar[0]);
    const uint32_t sm0 = smem_u32(dyn_smem);
    const char* src_base = (const char*)(xb + (size_t)(l0 - 4) * D4);
    const float4* smem_tid = dyn_smem + tid;
    float4* yb_tid = yb + tid;

    if (tid == 0) {
#pragma unroll
        for (int s = 0; s < NSTAGES; ++s) mbar_init(mb0 + 8u * s, 1);
    }
    __syncthreads();

    // Fill the whole ring: stages 0..5 always exist (min last_stage = 7).
    if (tid == 0) {
#pragma unroll
        for (int t = 0; t < NSTAGES; ++t) {
            mbar_expect_tx(mb0 + 8u * t, STAGE_BYTES);
            bulk_g2s(sm0 + (uint32_t)t * STAGE_BYTES,
                     src_base + (size_t)t * STAGE_BYTES,
                     STAGE_BYTES, mb0 + 8u * t);
        }
    }

    // Wait for stages 0,1 (rows l0-4 .. l0+3)
    mbar_wait(mb0 + 0u, 0u);
    mbar_wait(mb0 + 8u, 0u);

    // Left boundary: rows 0..7 are stages 0,1 of chunk 0.
    if (chunk == 0) {
        float4 e[8];
#pragma unroll
        for (int r = 0; r < 4; ++r) e[r]     = smem_tid[r * D4];
#pragma unroll
        for (int r = 0; r < 4; ++r) e[4 + r] = smem_tid[STAGE_F4 + r * D4];
        edge_iter(e);
#pragma unroll
        for (int k = 0; k < 4; ++k)
            yb_tid[(size_t)k * D4] = e[k];   // rows 0..3 (e[0] = fixed x[0])
    }

    // Prologue window: q[0] = rows l0-4..l0-1, q[1] = rows l0..l0+3
    float4 q[3][4];
#pragma unroll
    for (int r = 0; r < 4; ++r) q[0][r] = smem_tid[r * D4];
#pragma unroll
    for (int r = 0; r < 4; ++r) q[1][r] = smem_tid[STAGE_F4 + r * D4];

    __syncthreads();   // everyone done reading slots 0,1

    // Refill slots 0,1 with stages 6,7 (exist for every chunk: min last=7).
    if (tid == 0) {
#pragma unroll
        for (int t = NSTAGES; t < NSTAGES + 2; ++t) {
            const int slot = t % NSTAGES;
            mbar_expect_tx(mb0 + 8u * slot, STAGE_BYTES);
            bulk_g2s(sm0 + (uint32_t)slot * STAGE_BYTES,
                     src_base + (size_t)t * STAGE_BYTES,
                     STAGE_BYTES, mb0 + 8u * slot);
        }
    }

    // Main loop: bodies consume stage t = g+2; quad rotation period 3.
    int l = l0;
    int t = 2;
#pragma unroll 1
    for (int g = 0; g < ngroups; g += 3) {
        run_body<0, 1, 2>(q, t, l, last_stage, mb0, sm0, src_base, smem_tid, yb_tid, tid);
        ++t; l += 4;
        run_body<1, 2, 0>(q, t, l, last_stage, mb0, sm0, src_base, smem_tid, yb_tid, tid);
        ++t; l += 4;
        run_body<2, 0, 1>(q, t, l, last_stage, mb0, sm0, src_base, smem_tid, yb_tid, tid);
        ++t; l += 4;
    }

    // Right boundary: final window (q[0], q[1]) = rows L-8..L-1 for the last
    // chunk (ngroups % 3 == 0 -> rotation back to start).
    if (chunk == NCHUNK - 1) {
        float4 e[8];
#pragma unroll
        for (int r = 0; r < 4; ++r) { e[r] = q[0][r]; e[4 + r] = q[1][r]; }
        edge_iter(e);
#pragma unroll
        for (int k = 0; k < 4; ++k)
            yb_tid[(size_t)(L - 4 + k) * D4] = e[4 + k];  // rows L-4..L-1
    }
}

extern "C" void kernel_launch(void* const* d_in, const int* in_sizes, int n_in,
                              void* d_out, int out_size)
{
    const float* x = (const float*)d_in[0];
    float*       y = (float*)d_out;

    cudaFuncSetAttribute(mixer_kernel,
                         cudaFuncAttributeMaxDynamicSharedMemorySize,
                         RING_BYTES);

    mixer_kernel<<<dim3(NCHUNK, B), 256, RING_BYTES>>>(x, y);
}